// round 1
// baseline (speedup 1.0000x reference)
#include <cuda_runtime.h>
#include <cstdio>

// Problem constants (fixed-shape problem)
#define MAXN 50000
#define KDEG 16
#define F    64      // feature / LSTM hidden dim
#define G4   256     // 4*F gates

// ---------------- scratch (device globals: allocation-free) ----------------
__device__ float g_xp [MAXN * 64];    // projected feats (reused both layers)
__device__ float g_h1 [MAXN * 64];    // layer-1 SAGE output
__device__ float g_h2 [MAXN * 128];   // layer-2 SAGE output
__device__ float g_t1 [MAXN * 192];   // lin1 out
__device__ float g_t2 [MAXN * 64];    // lin2 out

// pre-transposed / concatenated weights
__device__ float g_wc1 [128 * 256];   // layer1 LSTM [k(128) x g(256)]  (k<64: wih, else whh)
__device__ float g_wc2 [128 * 256];
__device__ float g_bs1 [256];         // bih+bhh
__device__ float g_bs2 [256];
__device__ float g_wo1 [128 * 64];    // layer1 out-lin [k(128) x o]  (k<64: lr_w, else ll_w)
__device__ float g_wo2 [128 * 128];
__device__ float g_pT1 [64 * 64];     // proj weights transposed [k x o]
__device__ float g_pT2 [64 * 64];
__device__ float g_l1T [128 * 192];
__device__ float g_l2T [192 * 64];
__device__ float g_l3T [64 * 64];

// ---------------- activations ----------------
__device__ __forceinline__ float sigf(float x) {
    return __fdividef(1.0f, 1.0f + __expf(-x));
}
__device__ __forceinline__ float tanhfast(float x) {
    return __fdividef(2.0f, 1.0f + __expf(-2.0f * x)) - 1.0f;
}

// ---------------- prep kernels (tiny, once per launch) ----------------
__global__ void k_prep_lstm(float* wcat, float* bias,
                            const float* __restrict__ wih, const float* __restrict__ whh,
                            const float* __restrict__ bih, const float* __restrict__ bhh) {
    int idx = blockIdx.x * blockDim.x + threadIdx.x;
    if (idx < 128 * 256) {
        int k = idx >> 8, g = idx & 255;
        wcat[idx] = (k < 64) ? wih[g * 64 + k] : whh[g * 64 + (k - 64)];
    }
    if (idx < 256) bias[idx] = bih[idx] + bhh[idx];
}

__global__ void k_prep_out(float* woT, const float* __restrict__ llw,
                           const float* __restrict__ lrw, int OUT) {
    int idx = blockIdx.x * blockDim.x + threadIdx.x;
    if (idx < 128 * OUT) {
        int k = idx / OUT, o = idx - k * OUT;
        woT[idx] = (k < 64) ? lrw[o * 64 + k] : llw[o * 64 + (k - 64)];
    }
}

__global__ void k_transpose(float* dT, const float* __restrict__ w, int OUT, int IN) {
    int idx = blockIdx.x * blockDim.x + threadIdx.x;
    if (idx < IN * OUT) {
        int k = idx / OUT, o = idx - k * OUT;
        dT[idx] = w[o * IN + k];   // dT[k*OUT+o]
    }
}

__global__ void k_edge_copy(const int* __restrict__ ei, float* __restrict__ out, int count) {
    int i = blockIdx.x * blockDim.x + threadIdx.x;
    if (i < count) out[i] = (float)ei[i];
}

// ---------------- fused LSTM-SAGE kernel ----------------
// One block = 64 nodes. Shared: wcat [128k x 256g], in-state [64n x 128k] (x||h), c [64n x 64].
// Thread tile: 4 nodes x (2 hidden units x 4 gate types) -> full activation local to thread.
#define FMA_ROW(i, a)                                            \
    acc[i][0] += (a) * w0.x; acc[i][1] += (a) * w0.y;            \
    acc[i][2] += (a) * w1.x; acc[i][3] += (a) * w1.y;            \
    acc[i][4] += (a) * w2.x; acc[i][5] += (a) * w2.y;            \
    acc[i][6] += (a) * w3.x; acc[i][7] += (a) * w3.y;

template<int OUT>
__global__ __launch_bounds__(512, 1)
void lstm_sage_kernel(const float* __restrict__ xp,   // [N,64] projected (message) feats
                      const float* __restrict__ xin,  // [N,64] layer input (root feats)
                      const int*   __restrict__ src,  // [E]
                      const float* __restrict__ wcat, // [128*256]
                      const float* __restrict__ bias, // [256]
                      const float* __restrict__ woT,  // [128*OUT]
                      const float* __restrict__ ob,   // [OUT]
                      float* __restrict__ out,        // [N,OUT]
                      int N) {
    extern __shared__ float sm[];
    float* s_w   = sm;                 // 32768 floats
    float* s_in  = s_w + 32768;        // 8192  floats : [n][k], k<64 = x_t, k>=64 = h
    float* s_c   = s_in + 8192;        // 4096  floats : [n][j]
    float* s_b   = s_c + 4096;         // 256
    int*   s_src = (int*)(s_b + 256);  // 1024 ints

    const int tx   = threadIdx.x;
    const int base = blockIdx.x * 64;

    // load LSTM weights (coalesced float4, conflict-free stores)
    {
        const float4* wsrc = (const float4*)wcat;
        float4* wdst = (float4*)s_w;
        #pragma unroll
        for (int r = 0; r < 16; r++) wdst[tx + r * 512] = wsrc[tx + r * 512];
    }
    if (tx < 256) s_b[tx] = bias[tx];
    // src indices for this tile (guarded)
    #pragma unroll
    for (int r = 0; r < 2; r++) {
        int i = tx + r * 512;
        int node = base + (i >> 4);
        s_src[i] = (node < N) ? src[node * KDEG + (i & 15)] : 0;
    }
    // zero h and c
    {
        float4 z = make_float4(0.f, 0.f, 0.f, 0.f);
        float4* p = (float4*)s_in;
        #pragma unroll
        for (int r = 0; r < 4; r++) p[tx + r * 512] = z;
        float4* pc = (float4*)s_c;
        #pragma unroll
        for (int r = 0; r < 2; r++) pc[tx + r * 512] = z;
    }
    __syncthreads();

    const int jg = tx & 31, ng = tx >> 5;
    const int n0 = ng << 2, j0 = jg << 1;

    for (int t = 0; t < KDEG; t++) {
        // gather x_t = xp[src[node*16+t]] into s_in[n][0:64]
        #pragma unroll
        for (int r = 0; r < 8; r++) {
            int idx = tx + r * 512;            // 4096 = 64 rows * 64 feats
            int n = idx >> 6, f = idx & 63;
            s_in[n * 128 + f] = xp[(long)s_src[n * KDEG + t] * 64 + f];
        }
        __syncthreads();

        // GEMM: gates[64n x 256g] = s_in[64n x 128k] * s_w[128k x 256g] + bias
        float acc[4][8];
        #pragma unroll
        for (int i = 0; i < 4; i++) {
            #pragma unroll
            for (int q = 0; q < 4; q++) {
                acc[i][2 * q]     = s_b[q * 64 + j0];
                acc[i][2 * q + 1] = s_b[q * 64 + j0 + 1];
            }
        }
        #pragma unroll 4
        for (int k = 0; k < 128; k++) {
            float a0 = s_in[(n0 + 0) * 128 + k];
            float a1 = s_in[(n0 + 1) * 128 + k];
            float a2 = s_in[(n0 + 2) * 128 + k];
            float a3 = s_in[(n0 + 3) * 128 + k];
            const float* wr = s_w + k * 256 + j0;
            float2 w0 = *(const float2*)(wr + 0);     // i gates
            float2 w1 = *(const float2*)(wr + 64);    // f gates
            float2 w2 = *(const float2*)(wr + 128);   // g gates
            float2 w3 = *(const float2*)(wr + 192);   // o gates
            FMA_ROW(0, a0) FMA_ROW(1, a1) FMA_ROW(2, a2) FMA_ROW(3, a3)
        }
        __syncthreads();

        // activation + state update (each (n,j) owned by exactly one thread)
        #pragma unroll
        for (int i = 0; i < 4; i++) {
            int n = n0 + i;
            #pragma unroll
            for (int c = 0; c < 2; c++) {
                int j = j0 + c;
                float ig = sigf(acc[i][0 + c]);
                float fg = sigf(acc[i][2 + c]);
                float gg = tanhfast(acc[i][4 + c]);
                float og = sigf(acc[i][6 + c]);
                float cv = fg * s_c[n * 64 + j] + ig * gg;
                s_c[n * 64 + j] = cv;
                s_in[n * 128 + 64 + j] = og * tanhfast(cv);  // h -> second half of input
            }
        }
    }
    __syncthreads();

    // ---- fused SAGE output: out = relu( [x || h] * woT + ob ) ----
    for (int i = tx; i < 128 * OUT; i += 512) s_w[i] = woT[i];
    for (int i = tx; i < OUT; i += 512) s_b[i] = ob[i];
    #pragma unroll
    for (int r = 0; r < 8; r++) {
        int idx = tx + r * 512;
        int n = idx >> 6, f = idx & 63;
        int node = base + n;
        s_in[n * 128 + f] = (node < N) ? xin[(long)node * 64 + f] : 0.f;
    }
    __syncthreads();

    constexpr int CPT = OUT / 32;   // 2 or 4
    const int jo = jg * CPT;
    float a2[4][CPT];
    #pragma unroll
    for (int i = 0; i < 4; i++)
        #pragma unroll
        for (int c = 0; c < CPT; c++) a2[i][c] = s_b[jo + c];
    #pragma unroll 4
    for (int k = 0; k < 128; k++) {
        float b0 = s_in[(n0 + 0) * 128 + k];
        float b1 = s_in[(n0 + 1) * 128 + k];
        float b2 = s_in[(n0 + 2) * 128 + k];
        float b3 = s_in[(n0 + 3) * 128 + k];
        #pragma unroll
        for (int c = 0; c < CPT; c++) {
            float w = s_w[k * OUT + jo + c];
            a2[0][c] += b0 * w; a2[1][c] += b1 * w;
            a2[2][c] += b2 * w; a2[3][c] += b3 * w;
        }
    }
    #pragma unroll
    for (int i = 0; i < 4; i++) {
        int node = base + n0 + i;
        if (node < N) {
            #pragma unroll
            for (int c = 0; c < CPT; c++)
                out[(long)node * OUT + jo + c] = fmaxf(a2[i][c], 0.f);
        }
    }
}

// ---------------- generic fused linear+relu ----------------
template<int KIN, int KOUT>
__global__ __launch_bounds__(512, 1)
void linear_relu(const float* __restrict__ A, const float* __restrict__ WT,
                 const float* __restrict__ b, float* __restrict__ out, int N) {
    extern __shared__ float sm[];
    float* s_w = sm;                  // KIN*KOUT
    float* s_a = s_w + KIN * KOUT;    // 64*KIN
    float* s_b = s_a + 64 * KIN;      // KOUT
    const int tx = threadIdx.x;
    const int base = blockIdx.x * 64;

    for (int i = tx; i < (KIN * KOUT) / 4; i += 512)
        ((float4*)s_w)[i] = ((const float4*)WT)[i];
    for (int i = tx; i < KOUT; i += 512) s_b[i] = b[i];
    for (int v = tx; v < (64 * KIN) / 4; v += 512) {
        int elem = v * 4;
        int n = elem / KIN, f = elem - n * KIN;
        int node = base + n;
        float4 val = make_float4(0.f, 0.f, 0.f, 0.f);
        if (node < N) val = *(const float4*)(A + (long)node * KIN + f);
        *(float4*)(s_a + n * KIN + f) = val;
    }
    __syncthreads();

    const int jg = tx & 31, ng = tx >> 5;
    const int n0 = ng << 2;
    constexpr int CPT = KOUT / 32;
    const int jo = jg * CPT;
    float acc[4][CPT];
    #pragma unroll
    for (int i = 0; i < 4; i++)
        #pragma unroll
        for (int c = 0; c < CPT; c++) acc[i][c] = s_b[jo + c];
    #pragma unroll 4
    for (int k = 0; k < KIN; k++) {
        float a0 = s_a[(n0 + 0) * KIN + k];
        float a1 = s_a[(n0 + 1) * KIN + k];
        float a2 = s_a[(n0 + 2) * KIN + k];
        float a3 = s_a[(n0 + 3) * KIN + k];
        #pragma unroll
        for (int c = 0; c < CPT; c++) {
            float w = s_w[k * KOUT + jo + c];
            acc[0][c] += a0 * w; acc[1][c] += a1 * w;
            acc[2][c] += a2 * w; acc[3][c] += a3 * w;
        }
    }
    #pragma unroll
    for (int i = 0; i < 4; i++) {
        int node = base + n0 + i;
        if (node < N) {
            #pragma unroll
            for (int c = 0; c < CPT; c++)
                out[(long)node * KOUT + jo + c] = fmaxf(acc[i][c], 0.f);
        }
    }
}

// ---------------- host launcher ----------------
static void* symaddr(const void* sym) {
    void* p = nullptr;
    cudaGetSymbolAddress(&p, sym);
    return p;
}

extern "C" void kernel_launch(void* const* d_in, const int* in_sizes, int n_in,
                              void* d_out, int out_size) {
    const float* x   = (const float*)d_in[0];
    const int*   ei  = (const int*)d_in[1];
    const int N = in_sizes[0] / 64;
    const int E = in_sizes[1] / 2;
    const int* src = ei;   // edge_index row 0

    const float* p1pw  = (const float*)d_in[3];
    const float* p1pb  = (const float*)d_in[4];
    const float* p1wih = (const float*)d_in[5];
    const float* p1whh = (const float*)d_in[6];
    const float* p1bih = (const float*)d_in[7];
    const float* p1bhh = (const float*)d_in[8];
    const float* p1llw = (const float*)d_in[9];
    const float* p1llb = (const float*)d_in[10];
    const float* p1lrw = (const float*)d_in[11];
    const float* p2pw  = (const float*)d_in[12];
    const float* p2pb  = (const float*)d_in[13];
    const float* p2wih = (const float*)d_in[14];
    const float* p2whh = (const float*)d_in[15];
    const float* p2bih = (const float*)d_in[16];
    const float* p2bhh = (const float*)d_in[17];
    const float* p2llw = (const float*)d_in[18];
    const float* p2llb = (const float*)d_in[19];
    const float* p2lrw = (const float*)d_in[20];
    const float* l1w   = (const float*)d_in[21];
    const float* l1b   = (const float*)d_in[22];
    const float* l2w   = (const float*)d_in[23];
    const float* l2b   = (const float*)d_in[24];
    const float* l3w   = (const float*)d_in[25];
    const float* l3b   = (const float*)d_in[26];

    float* xp  = (float*)symaddr(g_xp);
    float* h1  = (float*)symaddr(g_h1);
    float* h2  = (float*)symaddr(g_h2);
    float* t1  = (float*)symaddr(g_t1);
    float* t2  = (float*)symaddr(g_t2);
    float* wc1 = (float*)symaddr(g_wc1);
    float* wc2 = (float*)symaddr(g_wc2);
    float* bs1 = (float*)symaddr(g_bs1);
    float* bs2 = (float*)symaddr(g_bs2);
    float* wo1 = (float*)symaddr(g_wo1);
    float* wo2 = (float*)symaddr(g_wo2);
    float* pT1 = (float*)symaddr(g_pT1);
    float* pT2 = (float*)symaddr(g_pT2);
    float* l1T = (float*)symaddr(g_l1T);
    float* l2T = (float*)symaddr(g_l2T);
    float* l3T = (float*)symaddr(g_l3T);

    // opt into large dynamic smem (idempotent host calls; not captured)
    const int SM_LSTM  = (32768 + 8192 + 4096 + 256) * 4 + 1024 * 4;       // 185344
    const int SM_L6464 = (64 * 64 + 64 * 64 + 64) * 4;                     // 33024
    const int SM_L1    = (128 * 192 + 64 * 128 + 192) * 4;                 // 131840
    const int SM_L2    = (192 * 64 + 64 * 192 + 64) * 4;                   // 98560
    cudaFuncSetAttribute(lstm_sage_kernel<64>,  cudaFuncAttributeMaxDynamicSharedMemorySize, SM_LSTM);
    cudaFuncSetAttribute(lstm_sage_kernel<128>, cudaFuncAttributeMaxDynamicSharedMemorySize, SM_LSTM);
    cudaFuncSetAttribute(linear_relu<64, 64>,   cudaFuncAttributeMaxDynamicSharedMemorySize, SM_L6464);
    cudaFuncSetAttribute(linear_relu<128, 192>, cudaFuncAttributeMaxDynamicSharedMemorySize, SM_L1);
    cudaFuncSetAttribute(linear_relu<192, 64>,  cudaFuncAttributeMaxDynamicSharedMemorySize, SM_L2);

    // --- weight prep ---
    k_prep_lstm<<<(128 * 256 + 255) / 256, 256>>>(wc1, bs1, p1wih, p1whh, p1bih, p1bhh);
    k_prep_lstm<<<(128 * 256 + 255) / 256, 256>>>(wc2, bs2, p2wih, p2whh, p2bih, p2bhh);
    k_prep_out<<<(128 * 64 + 255) / 256, 256>>>(wo1, p1llw, p1lrw, 64);
    k_prep_out<<<(128 * 128 + 255) / 256, 256>>>(wo2, p2llw, p2lrw, 128);
    k_transpose<<<(64 * 64 + 255) / 256, 256>>>(pT1, p1pw, 64, 64);
    k_transpose<<<(64 * 64 + 255) / 256, 256>>>(pT2, p2pw, 64, 64);
    k_transpose<<<(128 * 192 + 255) / 256, 256>>>(l1T, l1w, 192, 128);
    k_transpose<<<(192 * 64 + 255) / 256, 256>>>(l2T, l2w, 64, 192);
    k_transpose<<<(64 * 64 + 255) / 256, 256>>>(l3T, l3w, 64, 64);

    const int NB = (N + 63) / 64;

    // --- layer 1 ---
    linear_relu<64, 64><<<NB, 512, SM_L6464>>>(x, pT1, p1pb, xp, N);
    lstm_sage_kernel<64><<<NB, 512, SM_LSTM>>>(xp, x, src, wc1, bs1, wo1, p1llb, h1, N);
    // --- layer 2 ---
    linear_relu<64, 64><<<NB, 512, SM_L6464>>>(h1, pT2, p2pb, xp, N);
    lstm_sage_kernel<128><<<NB, 512, SM_LSTM>>>(xp, h1, src, wc2, bs2, wo2, p2llb, h2, N);
    // --- MLP head ---
    linear_relu<128, 192><<<NB, 512, SM_L1>>>(h2, l1T, l1b, t1, N);
    linear_relu<192, 64><<<NB, 512, SM_L2>>>(t1, l2T, l2b, t2, N);
    linear_relu<64, 64><<<NB, 512, SM_L6464>>>(t2, l3T, l3b, (float*)d_out, N);

    // --- edge_index passthrough (second tuple element), if the output buffer holds it ---
    long hsz = (long)N * 64;
    if ((long)out_size > hsz) {
        long remaining = (long)out_size - hsz;
        int count = (int)((remaining < (long)2 * E) ? remaining : (long)2 * E);
        k_edge_copy<<<(count + 255) / 256, 256>>>(ei, (float*)d_out + hsz, count);
    }
}

// round 2
// speedup vs baseline: 2.7672x; 2.7672x over previous
#include <cuda_runtime.h>
#include <cstdint>

// Problem constants (fixed-shape problem)
#define MAXN 50000
#define KDEG 16

#define SIN 132   // s_in row stride (floats) : 64 data + pad -> conflict-free frags
#define SW  264   // s_w  row stride (floats) : 256 data + pad -> conflict-free frags

// ---------------- scratch (device globals: allocation-free) ----------------
__device__ float g_xp [MAXN * 64];
__device__ float g_h1 [MAXN * 64];
__device__ float g_h2 [MAXN * 128];
__device__ float g_t1 [MAXN * 192];
__device__ float g_t2 [MAXN * 64];

__device__ float g_wc1 [128 * 256];   // permuted+tf32 LSTM weights [k x pcol]
__device__ float g_wc2 [128 * 256];
__device__ float g_bs1 [256];         // permuted bih+bhh
__device__ float g_bs2 [256];
__device__ float g_wo1 [128 * 64];
__device__ float g_wo2 [128 * 128];
__device__ float g_pT1 [64 * 64];
__device__ float g_pT2 [64 * 64];
__device__ float g_l1T [128 * 192];
__device__ float g_l2T [192 * 64];
__device__ float g_l3T [64 * 64];

// ---------------- helpers ----------------
__device__ __forceinline__ float sigf(float x) {
    return __fdividef(1.0f, 1.0f + __expf(-x));
}
__device__ __forceinline__ float tanhfast(float x) {
    return __fdividef(2.0f, 1.0f + __expf(-2.0f * x)) - 1.0f;
}
__device__ __forceinline__ float tf32r(float x) {
    uint32_t u;
    asm("cvt.rna.tf32.f32 %0, %1;" : "=r"(u) : "f"(x));
    return __uint_as_float(u);
}

#define MMA_TF32(D, A, b0, b1)                                                  \
    asm volatile("mma.sync.aligned.m16n8k8.row.col.f32.tf32.tf32.f32 "          \
                 "{%0,%1,%2,%3}, {%4,%5,%6,%7}, {%8,%9}, {%0,%1,%2,%3};"        \
                 : "+f"(D[0]), "+f"(D[1]), "+f"(D[2]), "+f"(D[3])               \
                 : "r"(A[0]), "r"(A[1]), "r"(A[2]), "r"(A[3]), "r"(b0), "r"(b1));

// Column permutation: gate columns reordered so each THREAD's mma accumulator
// fragment owns the full (i,f,g,o) quadruple of its hidden units.
// permuted col p -> original gate col g:
__device__ __forceinline__ int perm_orig_col(int p) {
    int nj = p >> 6, r = p & 63;
    int tp = r >> 4, r2 = r & 15;
    int half = r2 >> 3, r3 = r2 & 7;
    int q = r3 >> 1, low = r3 & 1;
    int gate = half * 2 + low;              // 0=i 1=f 2=g 3=o
    int jg = nj * 16 + q * 4 + tp;          // hidden unit index
    return gate * 64 + jg;
}

// ---------------- prep kernels ----------------
__global__ void k_prep_lstm_perm(float* wcat, float* bias,
                                 const float* __restrict__ wih, const float* __restrict__ whh,
                                 const float* __restrict__ bih, const float* __restrict__ bhh) {
    int idx = blockIdx.x * blockDim.x + threadIdx.x;
    if (idx < 128 * 256) {
        int k = idx >> 8, p = idx & 255;
        int g = perm_orig_col(p);
        float v = (k < 64) ? wih[g * 64 + k] : whh[g * 64 + (k - 64)];
        wcat[idx] = tf32r(v);
    }
    if (idx < 256) {
        int g = perm_orig_col(idx);
        bias[idx] = bih[g] + bhh[g];
    }
}

__global__ void k_prep_out(float* woT, const float* __restrict__ llw,
                           const float* __restrict__ lrw, int OUT) {
    int idx = blockIdx.x * blockDim.x + threadIdx.x;
    if (idx < 128 * OUT) {
        int k = idx / OUT, o = idx - k * OUT;
        woT[idx] = (k < 64) ? lrw[o * 64 + k] : llw[o * 64 + (k - 64)];
    }
}

__global__ void k_transpose(float* dT, const float* __restrict__ w, int OUT, int IN) {
    int idx = blockIdx.x * blockDim.x + threadIdx.x;
    if (idx < IN * OUT) {
        int k = idx / OUT, o = idx - k * OUT;
        dT[idx] = w[o * IN + k];
    }
}

__global__ void k_edge_copy(const int* __restrict__ ei, float* __restrict__ out, int count) {
    int i = blockIdx.x * blockDim.x + threadIdx.x;
    if (i < count) out[i] = (float)ei[i];
}

// ---------------- fused LSTM-SAGE kernel (tf32 mma.sync) ----------------
// Block = 64 nodes, 256 threads = 8 warps, warp grid 2(m32) x 4(n64).
// c-state fully register-resident via gate-column permutation.
template<int OUT>
__global__ __launch_bounds__(256, 1)
void lstm_mma_kernel(const float* __restrict__ xp,   // [N,64] projected msgs
                     const float* __restrict__ xin,  // [N,64] root feats
                     const int*   __restrict__ src,  // [E]
                     const float* __restrict__ wcat, // [128*256] permuted tf32
                     const float* __restrict__ bias, // [256] permuted
                     const float* __restrict__ woT,  // [128*OUT]
                     const float* __restrict__ ob,   // [OUT]
                     float* __restrict__ out,        // [N,OUT]
                     int N) {
    extern __shared__ float sm[];
    float* s_w   = sm;                      // 128*264 floats
    float* s_in  = s_w + 128 * SW;          // 64*132 floats  ([x_t | h] rows)
    float* s_b   = s_in + 64 * SIN;         // 256
    int*   s_src = (int*)(s_b + 256);       // 1024

    const int tx = threadIdx.x;
    const int base = blockIdx.x * 64;
    const int lane = tx & 31, w = tx >> 5;
    const int mg = w >> 2, nj = w & 3;
    const int nwb = nj * 64;
    const int mr = mg * 32;
    const int r = lane >> 2, q = lane & 3;

    // load permuted LSTM weights into padded smem (float4, conflict-light)
    for (int i = tx; i < 128 * 64; i += 256) {       // 64 float4 per row
        int row = i >> 6, c4 = i & 63;
        float4 v = ((const float4*)wcat)[i];
        *(float4*)&s_w[row * SW + c4 * 4] = v;
    }
    if (tx < 256) s_b[tx] = bias[tx];
    for (int i = tx; i < 1024; i += 256) {
        int node = base + (i >> 4);
        s_src[i] = (node < N) ? src[node * KDEG + (i & 15)] : 0;
    }
    for (int i = tx; i < 64 * SIN; i += 256) s_in[i] = 0.f;
    __syncthreads();

    // per-thread bias for its 16 accumulator columns
    float bs0[8], bs1[8];
    #pragma unroll
    for (int nt = 0; nt < 8; nt++) {
        bs0[nt] = s_b[nwb + nt * 8 + 2 * q];
        bs1[nt] = s_b[nwb + nt * 8 + 2 * q + 1];
    }
    // register-resident cell state: [mt][Tpair][rr]
    float cst[2][4][2];
    #pragma unroll
    for (int a = 0; a < 2; a++)
        #pragma unroll
        for (int b = 0; b < 4; b++) { cst[a][b][0] = 0.f; cst[a][b][1] = 0.f; }

    auto gather = [&](int t) {
        #pragma unroll
        for (int i = 0; i < 4; i++) {
            int idx = tx + i * 256;
            int n = idx >> 4, c4 = idx & 15;
            const float4 v = *(const float4*)(xp + (size_t)s_src[n * KDEG + t] * 64 + c4 * 4);
            float4 o;
            o.x = tf32r(v.x); o.y = tf32r(v.y); o.z = tf32r(v.z); o.w = tf32r(v.w);
            *(float4*)&s_in[n * SIN + c4 * 4] = o;
        }
    };

    gather(0);

    for (int t = 0; t < KDEG; t++) {
        __syncthreads();   // gather + h writes visible

        float acc[2][8][4];
        #pragma unroll
        for (int mt = 0; mt < 2; mt++)
            #pragma unroll
            for (int nt = 0; nt < 8; nt++) {
                acc[mt][nt][0] = bs0[nt]; acc[mt][nt][1] = bs1[nt];
                acc[mt][nt][2] = bs0[nt]; acc[mt][nt][3] = bs1[nt];
            }

        #pragma unroll 4
        for (int kk = 0; kk < 128; kk += 8) {
            uint32_t afr[2][4];
            #pragma unroll
            for (int mt = 0; mt < 2; mt++) {
                const float* ap = s_in + (mr + mt * 16 + r) * SIN + kk + q;
                afr[mt][0] = __float_as_uint(ap[0]);
                afr[mt][1] = __float_as_uint(ap[8 * SIN]);
                afr[mt][2] = __float_as_uint(ap[4]);
                afr[mt][3] = __float_as_uint(ap[8 * SIN + 4]);
            }
            #pragma unroll
            for (int nt = 0; nt < 8; nt++) {
                const float* bp = s_w + (kk + q) * SW + nwb + nt * 8 + r;
                uint32_t b0 = __float_as_uint(bp[0]);
                uint32_t b1 = __float_as_uint(bp[4 * SW]);
                MMA_TF32(acc[0][nt], afr[0], b0, b1);
                MMA_TF32(acc[1][nt], afr[1], b0, b1);
            }
        }
        __syncthreads();   // all s_in reads done

        // activation: (i,f,g,o) fully thread-local thanks to permutation
        #pragma unroll
        for (int mt = 0; mt < 2; mt++) {
            #pragma unroll
            for (int tp = 0; tp < 4; tp++) {
                #pragma unroll
                for (int rr = 0; rr < 2; rr++) {
                    float iv = acc[mt][2 * tp][rr * 2 + 0];
                    float fv = acc[mt][2 * tp][rr * 2 + 1];
                    float gv = acc[mt][2 * tp + 1][rr * 2 + 0];
                    float ov = acc[mt][2 * tp + 1][rr * 2 + 1];
                    float c = sigf(fv) * cst[mt][tp][rr] + sigf(iv) * tanhfast(gv);
                    cst[mt][tp][rr] = c;
                    float h = sigf(ov) * tanhfast(c);
                    int row = mr + mt * 16 + r + 8 * rr;
                    s_in[row * SIN + 64 + nj * 16 + q * 4 + tp] = tf32r(h);
                }
            }
        }
        if (t + 1 < KDEG) gather(t + 1);   // writes cols 0..63, disjoint from h
    }

    // ---- fused SAGE output: out = relu([x || h] * woT + ob), FFMA path ----
    for (int i = tx; i < (128 * OUT) / 4; i += 256)
        ((float4*)s_w)[i] = ((const float4*)woT)[i];
    for (int i = tx; i < OUT; i += 256) s_b[i] = ob[i];
    #pragma unroll
    for (int i = 0; i < 4; i++) {
        int idx = tx + i * 256;
        int n = idx >> 4, c4 = idx & 15;
        int node = base + n;
        float4 v = make_float4(0.f, 0.f, 0.f, 0.f);
        if (node < N) v = *(const float4*)(xin + (size_t)node * 64 + c4 * 4);
        *(float4*)&s_in[n * SIN + c4 * 4] = v;
    }
    __syncthreads();

    constexpr int CPT = OUT / 32;
    const int grp = tx >> 5;
    const int n0 = grp * 8;
    float a2[8][CPT];
    #pragma unroll
    for (int i = 0; i < 8; i++)
        #pragma unroll
        for (int c = 0; c < CPT; c++) a2[i][c] = s_b[lane + 32 * c];
    #pragma unroll 4
    for (int k = 0; k < 128; k++) {
        float wv[CPT];
        #pragma unroll
        for (int c = 0; c < CPT; c++) wv[c] = s_w[k * OUT + lane + 32 * c];
        #pragma unroll
        for (int i = 0; i < 8; i++) {
            float av = s_in[(n0 + i) * SIN + k];
            #pragma unroll
            for (int c = 0; c < CPT; c++) a2[i][c] += av * wv[c];
        }
    }
    #pragma unroll
    for (int i = 0; i < 8; i++) {
        int node = base + n0 + i;
        if (node < N) {
            #pragma unroll
            for (int c = 0; c < CPT; c++)
                out[(size_t)node * OUT + lane + 32 * c] = fmaxf(a2[i][c], 0.f);
        }
    }
}

// ---------------- generic fused linear+relu (FFMA) ----------------
template<int KIN, int KOUT>
__global__ __launch_bounds__(512, 1)
void linear_relu(const float* __restrict__ A, const float* __restrict__ WT,
                 const float* __restrict__ b, float* __restrict__ out, int N) {
    extern __shared__ float sm[];
    float* s_w = sm;
    float* s_a = s_w + KIN * KOUT;
    float* s_b = s_a + 64 * KIN;
    const int tx = threadIdx.x;
    const int base = blockIdx.x * 64;

    for (int i = tx; i < (KIN * KOUT) / 4; i += 512)
        ((float4*)s_w)[i] = ((const float4*)WT)[i];
    for (int i = tx; i < KOUT; i += 512) s_b[i] = b[i];
    for (int v = tx; v < (64 * KIN) / 4; v += 512) {
        int elem = v * 4;
        int n = elem / KIN, f = elem - n * KIN;
        int node = base + n;
        float4 val = make_float4(0.f, 0.f, 0.f, 0.f);
        if (node < N) val = *(const float4*)(A + (size_t)node * KIN + f);
        *(float4*)(s_a + n * KIN + f) = val;
    }
    __syncthreads();

    const int jg = tx & 31, ng = tx >> 5;
    const int n0 = ng << 2;
    constexpr int CPT = KOUT / 32;
    const int jo = jg * CPT;
    float acc[4][CPT];
    #pragma unroll
    for (int i = 0; i < 4; i++)
        #pragma unroll
        for (int c = 0; c < CPT; c++) acc[i][c] = s_b[jo + c];
    #pragma unroll 4
    for (int k = 0; k < KIN; k++) {
        float a0 = s_a[(n0 + 0) * KIN + k];
        float a1 = s_a[(n0 + 1) * KIN + k];
        float a2 = s_a[(n0 + 2) * KIN + k];
        float a3 = s_a[(n0 + 3) * KIN + k];
        #pragma unroll
        for (int c = 0; c < CPT; c++) {
            float wv = s_w[k * KOUT + jo + c];
            acc[0][c] += a0 * wv; acc[1][c] += a1 * wv;
            acc[2][c] += a2 * wv; acc[3][c] += a3 * wv;
        }
    }
    #pragma unroll
    for (int i = 0; i < 4; i++) {
        int node = base + n0 + i;
        if (node < N) {
            #pragma unroll
            for (int c = 0; c < CPT; c++)
                out[(size_t)node * KOUT + jo + c] = fmaxf(acc[i][c], 0.f);
        }
    }
}

// ---------------- host launcher ----------------
static void* symaddr(const void* sym) {
    void* p = nullptr;
    cudaGetSymbolAddress(&p, sym);
    return p;
}

extern "C" void kernel_launch(void* const* d_in, const int* in_sizes, int n_in,
                              void* d_out, int out_size) {
    const float* x   = (const float*)d_in[0];
    const int*   ei  = (const int*)d_in[1];
    const int N = in_sizes[0] / 64;
    const int E = in_sizes[1] / 2;
    const int* src = ei;

    const float* p1pw  = (const float*)d_in[3];
    const float* p1pb  = (const float*)d_in[4];
    const float* p1wih = (const float*)d_in[5];
    const float* p1whh = (const float*)d_in[6];
    const float* p1bih = (const float*)d_in[7];
    const float* p1bhh = (const float*)d_in[8];
    const float* p1llw = (const float*)d_in[9];
    const float* p1llb = (const float*)d_in[10];
    const float* p1lrw = (const float*)d_in[11];
    const float* p2pw  = (const float*)d_in[12];
    const float* p2pb  = (const float*)d_in[13];
    const float* p2wih = (const float*)d_in[14];
    const float* p2whh = (const float*)d_in[15];
    const float* p2bih = (const float*)d_in[16];
    const float* p2bhh = (const float*)d_in[17];
    const float* p2llw = (const float*)d_in[18];
    const float* p2llb = (const float*)d_in[19];
    const float* p2lrw = (const float*)d_in[20];
    const float* l1w   = (const float*)d_in[21];
    const float* l1b   = (const float*)d_in[22];
    const float* l2w   = (const float*)d_in[23];
    const float* l2b   = (const float*)d_in[24];
    const float* l3w   = (const float*)d_in[25];
    const float* l3b   = (const float*)d_in[26];

    float* xp  = (float*)symaddr(g_xp);
    float* h1  = (float*)symaddr(g_h1);
    float* h2  = (float*)symaddr(g_h2);
    float* t1  = (float*)symaddr(g_t1);
    float* t2  = (float*)symaddr(g_t2);
    float* wc1 = (float*)symaddr(g_wc1);
    float* wc2 = (float*)symaddr(g_wc2);
    float* bs1 = (float*)symaddr(g_bs1);
    float* bs2 = (float*)symaddr(g_bs2);
    float* wo1 = (float*)symaddr(g_wo1);
    float* wo2 = (float*)symaddr(g_wo2);
    float* pT1 = (float*)symaddr(g_pT1);
    float* pT2 = (float*)symaddr(g_pT2);
    float* l1T = (float*)symaddr(g_l1T);
    float* l2T = (float*)symaddr(g_l2T);
    float* l3T = (float*)symaddr(g_l3T);

    const int SM_LSTM  = (128 * SW + 64 * SIN + 256) * 4 + 1024 * 4;   // 174080
    const int SM_L6464 = (64 * 64 + 64 * 64 + 64) * 4;
    const int SM_L1    = (128 * 192 + 64 * 128 + 192) * 4;
    const int SM_L2    = (192 * 64 + 64 * 192 + 64) * 4;
    cudaFuncSetAttribute(lstm_mma_kernel<64>,   cudaFuncAttributeMaxDynamicSharedMemorySize, SM_LSTM);
    cudaFuncSetAttribute(lstm_mma_kernel<128>,  cudaFuncAttributeMaxDynamicSharedMemorySize, SM_LSTM);
    cudaFuncSetAttribute(linear_relu<64, 64>,   cudaFuncAttributeMaxDynamicSharedMemorySize, SM_L6464);
    cudaFuncSetAttribute(linear_relu<128, 192>, cudaFuncAttributeMaxDynamicSharedMemorySize, SM_L1);
    cudaFuncSetAttribute(linear_relu<192, 64>,  cudaFuncAttributeMaxDynamicSharedMemorySize, SM_L2);

    // --- weight prep ---
    k_prep_lstm_perm<<<(128 * 256 + 255) / 256, 256>>>(wc1, bs1, p1wih, p1whh, p1bih, p1bhh);
    k_prep_lstm_perm<<<(128 * 256 + 255) / 256, 256>>>(wc2, bs2, p2wih, p2whh, p2bih, p2bhh);
    k_prep_out<<<(128 * 64 + 255) / 256, 256>>>(wo1, p1llw, p1lrw, 64);
    k_prep_out<<<(128 * 128 + 255) / 256, 256>>>(wo2, p2llw, p2lrw, 128);
    k_transpose<<<(64 * 64 + 255) / 256, 256>>>(pT1, p1pw, 64, 64);
    k_transpose<<<(64 * 64 + 255) / 256, 256>>>(pT2, p2pw, 64, 64);
    k_transpose<<<(128 * 192 + 255) / 256, 256>>>(l1T, l1w, 192, 128);
    k_transpose<<<(192 * 64 + 255) / 256, 256>>>(l2T, l2w, 64, 192);
    k_transpose<<<(64 * 64 + 255) / 256, 256>>>(l3T, l3w, 64, 64);

    const int NB = (N + 63) / 64;

    // --- layer 1 ---
    linear_relu<64, 64><<<NB, 512, SM_L6464>>>(x, pT1, p1pb, xp, N);
    lstm_mma_kernel<64><<<NB, 256, SM_LSTM>>>(xp, x, src, wc1, bs1, wo1, p1llb, h1, N);
    // --- layer 2 ---
    linear_relu<64, 64><<<NB, 512, SM_L6464>>>(h1, pT2, p2pb, xp, N);
    lstm_mma_kernel<128><<<NB, 256, SM_LSTM>>>(xp, h1, src, wc2, bs2, wo2, p2llb, h2, N);
    // --- MLP head ---
    linear_relu<128, 192><<<NB, 512, SM_L1>>>(h2, l1T, l1b, t1, N);
    linear_relu<192, 64><<<NB, 512, SM_L2>>>(t1, l2T, l2b, t2, N);
    linear_relu<64, 64><<<NB, 512, SM_L6464>>>(t2, l3T, l3b, (float*)d_out, N);

    // --- edge_index passthrough if the output buffer holds it ---
    long hsz = (long)N * 64;
    if ((long)out_size > hsz) {
        long remaining = (long)out_size - hsz;
        int count = (int)((remaining < (long)2 * E) ? remaining : (long)2 * E);
        k_edge_copy<<<(count + 255) / 256, 256>>>(ei, (float*)d_out + hsz, count);
    }
}

// round 3
// speedup vs baseline: 3.6802x; 1.3300x over previous
#include <cuda_runtime.h>
#include <cstdint>

// Problem constants (fixed-shape problem)
#define MAXN 50000
#define KDEG 16

#define SIN 132   // s_in row stride (floats): 128 data + pad (bank-conflict-free frags)
#define SW  264   // s_w  row stride (floats): 256 data + pad

// ---------------- scratch (device globals: allocation-free) ----------------
__device__ float g_xp [MAXN * 64];
__device__ float g_h1 [MAXN * 64];
__device__ float g_h2 [MAXN * 128];
__device__ float g_t1 [MAXN * 192];
__device__ float g_t2 [MAXN * 64];

__device__ float g_wc1 [128 * 256];   // permuted+tf32 LSTM weights [k x pcol]
__device__ float g_wc2 [128 * 256];
__device__ float g_bs1 [256];
__device__ float g_bs2 [256];
__device__ float g_wo1 [128 * 64];    // [k x o], tf32
__device__ float g_wo2 [128 * 128];
__device__ float g_pT1 [64 * 64];
__device__ float g_pT2 [64 * 64];
__device__ float g_l1T [128 * 192];
__device__ float g_l2T [192 * 64];
__device__ float g_l3T [64 * 64];

// ---------------- helpers ----------------
__device__ __forceinline__ float tanha(float x) {
    float y;
    asm("tanh.approx.f32 %0, %1;" : "=f"(y) : "f"(x));
    return y;
}
__device__ __forceinline__ float sigt(float x) {      // sigmoid via tanh: 1 MUFU + 1 FMA
    return fmaf(tanha(0.5f * x), 0.5f, 0.5f);
}
__device__ __forceinline__ float tf32r(float x) {
    uint32_t u;
    asm("cvt.rna.tf32.f32 %0, %1;" : "=r"(u) : "f"(x));
    return __uint_as_float(u);
}

#define MMA_TF32(D, A, b0, b1)                                                  \
    asm volatile("mma.sync.aligned.m16n8k8.row.col.f32.tf32.tf32.f32 "          \
                 "{%0,%1,%2,%3}, {%4,%5,%6,%7}, {%8,%9}, {%0,%1,%2,%3};"        \
                 : "+f"(D[0]), "+f"(D[1]), "+f"(D[2]), "+f"(D[3])               \
                 : "r"(A[0]), "r"(A[1]), "r"(A[2]), "r"(A[3]), "r"(b0), "r"(b1));

// Gate-column permutation: each thread's accumulator fragment owns the full
// (i,f,g,o) quadruple for its hidden units -> c-state register-resident.
__device__ __forceinline__ int perm_orig_col(int p) {
    int nj = p >> 6, r = p & 63;
    int tp = r >> 4, r2 = r & 15;
    int half = r2 >> 3, r3 = r2 & 7;
    int q = r3 >> 1, low = r3 & 1;
    int gate = half * 2 + low;              // 0=i 1=f 2=g 3=o
    int jg = nj * 16 + q * 4 + tp;
    return gate * 64 + jg;
}

// ---------------- prep kernels ----------------
__global__ void k_prep_lstm_perm(float* wcat, float* bias,
                                 const float* __restrict__ wih, const float* __restrict__ whh,
                                 const float* __restrict__ bih, const float* __restrict__ bhh) {
    int idx = blockIdx.x * blockDim.x + threadIdx.x;
    if (idx < 128 * 256) {
        int k = idx >> 8, p = idx & 255;
        int g = perm_orig_col(p);
        float v = (k < 64) ? wih[g * 64 + k] : whh[g * 64 + (k - 64)];
        wcat[idx] = tf32r(v);
    }
    if (idx < 256) {
        int g = perm_orig_col(idx);
        bias[idx] = bih[g] + bhh[g];
    }
}

__global__ void k_prep_out(float* woT, const float* __restrict__ llw,
                           const float* __restrict__ lrw, int OUT) {
    int idx = blockIdx.x * blockDim.x + threadIdx.x;
    if (idx < 128 * OUT) {
        int k = idx / OUT, o = idx - k * OUT;
        woT[idx] = tf32r((k < 64) ? lrw[o * 64 + k] : llw[o * 64 + (k - 64)]);
    }
}

__global__ void k_transpose_tf32(float* dT, const float* __restrict__ w, int OUT, int IN) {
    int idx = blockIdx.x * blockDim.x + threadIdx.x;
    if (idx < IN * OUT) {
        int k = idx / OUT, o = idx - k * OUT;
        dT[idx] = tf32r(w[o * IN + k]);
    }
}

__global__ void k_edge_copy(const int* __restrict__ ei, float* __restrict__ out, int count) {
    int i = blockIdx.x * blockDim.x + threadIdx.x;
    if (i < count) out[i] = (float)ei[i];
}

// ---------------- fused LSTM-SAGE kernel (tf32 mma.sync, M=128/block) ----------------
// Block = 128 nodes, 256 threads = 8 warps, warp grid 2(m64) x 4(n64).
template<int OUT>
__global__ __launch_bounds__(256, 1)
void lstm_mma_kernel(const float* __restrict__ xp,
                     const float* __restrict__ xin,
                     const int*   __restrict__ src,
                     const float* __restrict__ wcat,
                     const float* __restrict__ bias,
                     const float* __restrict__ woT,   // [128 x OUT] tf32
                     const float* __restrict__ ob,
                     float* __restrict__ out,
                     int N) {
    extern __shared__ float sm[];
    float* s_w   = sm;                      // 128*SW
    float* s_in  = s_w + 128 * SW;          // 128*SIN ([x_t | h] rows)
    float* s_b   = s_in + 128 * SIN;        // 256
    int*   s_src = (int*)(s_b + 256);       // 2048

    const int tx = threadIdx.x;
    const int base = blockIdx.x * 128;
    const int lane = tx & 31, w = tx >> 5;
    const int mg = w >> 2, nj = w & 3;
    const int nwb = nj * 64;
    const int mrow = mg * 64;
    const int r = lane >> 2, q = lane & 3;

    for (int i = tx; i < 128 * 64; i += 256) {
        int row = i >> 6, c4 = i & 63;
        ((float4*)&s_w[row * SW])[c4] = ((const float4*)wcat)[i];
    }
    if (tx < 256) s_b[tx] = bias[tx];
    for (int i = tx; i < 2048; i += 256) {
        int node = base + (i >> 4);
        s_src[i] = (node < N) ? src[node * KDEG + (i & 15)] : 0;
    }
    for (int i = tx; i < 128 * SIN; i += 256) s_in[i] = 0.f;
    __syncthreads();

    float bs0[8], bs1[8];
    #pragma unroll
    for (int nt = 0; nt < 8; nt++) {
        bs0[nt] = s_b[nwb + nt * 8 + 2 * q];
        bs1[nt] = s_b[nwb + nt * 8 + 2 * q + 1];
    }
    float cst[4][4][2];
    #pragma unroll
    for (int a = 0; a < 4; a++)
        #pragma unroll
        for (int b = 0; b < 4; b++) { cst[a][b][0] = 0.f; cst[a][b][1] = 0.f; }

    auto gather = [&](int t) {
        #pragma unroll
        for (int i = 0; i < 8; i++) {
            int idx = tx + i * 256;              // 2048 = 128 rows * 16 float4
            int n = idx >> 4, c4 = idx & 15;
            const float4 v = *(const float4*)(xp + (size_t)s_src[n * KDEG + t] * 64 + c4 * 4);
            float4 o;
            o.x = tf32r(v.x); o.y = tf32r(v.y); o.z = tf32r(v.z); o.w = tf32r(v.w);
            *(float4*)&s_in[n * SIN + c4 * 4] = o;
        }
    };

    gather(0);

    for (int t = 0; t < KDEG; t++) {
        __syncthreads();   // gather + h writes visible

        float acc[4][8][4];
        #pragma unroll
        for (int mt = 0; mt < 4; mt++)
            #pragma unroll
            for (int nt = 0; nt < 8; nt++) {
                acc[mt][nt][0] = bs0[nt]; acc[mt][nt][1] = bs1[nt];
                acc[mt][nt][2] = bs0[nt]; acc[mt][nt][3] = bs1[nt];
            }

        #pragma unroll 2
        for (int kk = 0; kk < 128; kk += 8) {
            uint32_t afr[4][4];
            #pragma unroll
            for (int mt = 0; mt < 4; mt++) {
                const float* ap = s_in + (mrow + mt * 16 + r) * SIN + kk + q;
                afr[mt][0] = __float_as_uint(ap[0]);
                afr[mt][1] = __float_as_uint(ap[8 * SIN]);
                afr[mt][2] = __float_as_uint(ap[4]);
                afr[mt][3] = __float_as_uint(ap[8 * SIN + 4]);
            }
            #pragma unroll
            for (int nt = 0; nt < 8; nt++) {
                const float* bp = s_w + (kk + q) * SW + nwb + nt * 8 + r;
                uint32_t b0 = __float_as_uint(bp[0]);
                uint32_t b1 = __float_as_uint(bp[4 * SW]);
                MMA_TF32(acc[0][nt], afr[0], b0, b1);
                MMA_TF32(acc[1][nt], afr[1], b0, b1);
                MMA_TF32(acc[2][nt], afr[2], b0, b1);
                MMA_TF32(acc[3][nt], afr[3], b0, b1);
            }
        }
        __syncthreads();   // s_in reads done

        // activation: 1 MUFU per tanh/sigmoid (tanh.approx)
        #pragma unroll
        for (int mt = 0; mt < 4; mt++) {
            #pragma unroll
            for (int tp = 0; tp < 4; tp++) {
                #pragma unroll
                for (int rr = 0; rr < 2; rr++) {
                    float iv = acc[mt][2 * tp][rr * 2 + 0];
                    float fv = acc[mt][2 * tp][rr * 2 + 1];
                    float gv = acc[mt][2 * tp + 1][rr * 2 + 0];
                    float ov = acc[mt][2 * tp + 1][rr * 2 + 1];
                    float c = sigt(fv) * cst[mt][tp][rr] + sigt(iv) * tanha(gv);
                    cst[mt][tp][rr] = c;
                    float h = sigt(ov) * tanha(c);
                    int row = mrow + mt * 16 + r + 8 * rr;
                    s_in[row * SIN + 64 + nj * 16 + q * 4 + tp] = tf32r(h);
                }
            }
        }
        if (t + 1 < KDEG) gather(t + 1);   // cols 0..63, disjoint from h cols
    }

    // ---- fused SAGE output via MMA: out = relu([x || h] * woT + ob) ----
    constexpr int NT2 = OUT / 32;          // 2 or 4
    const int NPJ = OUT / 4;
    const int nwb2 = nj * NPJ;

    for (int i = tx; i < 128 * (OUT / 4); i += 256) {
        int row = i / (OUT / 4), c4 = i % (OUT / 4);
        ((float4*)&s_w[row * SW])[c4] = ((const float4*)woT)[i];
    }
    for (int i = tx; i < OUT; i += 256) s_b[i] = ob[i];
    #pragma unroll
    for (int i = 0; i < 8; i++) {
        int idx = tx + i * 256;
        int n = idx >> 4, c4 = idx & 15;
        int node = base + n;
        float4 v = make_float4(0.f, 0.f, 0.f, 0.f);
        if (node < N) v = *(const float4*)(xin + (size_t)node * 64 + c4 * 4);
        float4 o;
        o.x = tf32r(v.x); o.y = tf32r(v.y); o.z = tf32r(v.z); o.w = tf32r(v.w);
        *(float4*)&s_in[n * SIN + c4 * 4] = o;
    }
    __syncthreads();

    float a2[4][NT2][4];
    #pragma unroll
    for (int mt = 0; mt < 4; mt++)
        #pragma unroll
        for (int nt = 0; nt < NT2; nt++) {
            int c0 = nwb2 + nt * 8 + 2 * q;
            a2[mt][nt][0] = s_b[c0];     a2[mt][nt][1] = s_b[c0 + 1];
            a2[mt][nt][2] = s_b[c0];     a2[mt][nt][3] = s_b[c0 + 1];
        }
    #pragma unroll 4
    for (int kk = 0; kk < 128; kk += 8) {
        uint32_t afr[4][4];
        #pragma unroll
        for (int mt = 0; mt < 4; mt++) {
            const float* ap = s_in + (mrow + mt * 16 + r) * SIN + kk + q;
            afr[mt][0] = __float_as_uint(ap[0]);
            afr[mt][1] = __float_as_uint(ap[8 * SIN]);
            afr[mt][2] = __float_as_uint(ap[4]);
            afr[mt][3] = __float_as_uint(ap[8 * SIN + 4]);
        }
        #pragma unroll
        for (int nt = 0; nt < NT2; nt++) {
            const float* bp = s_w + (kk + q) * SW + nwb2 + nt * 8 + r;
            uint32_t b0 = __float_as_uint(bp[0]);
            uint32_t b1 = __float_as_uint(bp[4 * SW]);
            MMA_TF32(a2[0][nt], afr[0], b0, b1);
            MMA_TF32(a2[1][nt], afr[1], b0, b1);
            MMA_TF32(a2[2][nt], afr[2], b0, b1);
            MMA_TF32(a2[3][nt], afr[3], b0, b1);
        }
    }
    #pragma unroll
    for (int mt = 0; mt < 4; mt++)
        #pragma unroll
        for (int nt = 0; nt < NT2; nt++)
            #pragma unroll
            for (int rr = 0; rr < 2; rr++) {
                int node = base + mrow + mt * 16 + r + 8 * rr;
                if (node < N) {
                    int c0 = nwb2 + nt * 8 + 2 * q;
                    float2 v;
                    v.x = fmaxf(a2[mt][nt][2 * rr + 0], 0.f);
                    v.y = fmaxf(a2[mt][nt][2 * rr + 1], 0.f);
                    *(float2*)(out + (size_t)node * OUT + c0) = v;
                }
            }
}

// ---------------- tf32 MMA linear+relu ----------------
template<int KIN, int KOUT>
__global__ __launch_bounds__(256, 1)
void mma_linear(const float* __restrict__ A, const float* __restrict__ WT,
                const float* __restrict__ b, float* __restrict__ out, int N) {
    constexpr int SINL = KIN + 4, SWL = KOUT + 8;
    constexpr int NT = KOUT / 32, NPJ = KOUT / 4;
    extern __shared__ float sm[];
    float* s_w  = sm;
    float* s_in = s_w + KIN * SWL;
    float* s_b  = s_in + 128 * SINL;

    const int tx = threadIdx.x, base = blockIdx.x * 128;
    const int lane = tx & 31, w = tx >> 5;
    const int mg = w >> 2, nj = w & 3;
    const int r = lane >> 2, q = lane & 3;
    const int mrow = mg * 64, nwb = nj * NPJ;

    for (int i = tx; i < KIN * (KOUT / 4); i += 256) {
        int row = i / (KOUT / 4), c4 = i % (KOUT / 4);
        ((float4*)&s_w[row * SWL])[c4] = ((const float4*)WT)[i];
    }
    for (int i = tx; i < KOUT; i += 256) s_b[i] = b[i];
    for (int i = tx; i < 128 * (KIN / 4); i += 256) {
        int n = i / (KIN / 4), c4 = i % (KIN / 4);
        int node = base + n;
        float4 v = make_float4(0.f, 0.f, 0.f, 0.f);
        if (node < N) v = *(const float4*)(A + (size_t)node * KIN + c4 * 4);
        float4 o;
        o.x = tf32r(v.x); o.y = tf32r(v.y); o.z = tf32r(v.z); o.w = tf32r(v.w);
        *(float4*)&s_in[n * SINL + c4 * 4] = o;
    }
    __syncthreads();

    float acc[4][NT][4];
    #pragma unroll
    for (int mt = 0; mt < 4; mt++)
        #pragma unroll
        for (int nt = 0; nt < NT; nt++) {
            int c0 = nwb + nt * 8 + 2 * q;
            acc[mt][nt][0] = s_b[c0];     acc[mt][nt][1] = s_b[c0 + 1];
            acc[mt][nt][2] = s_b[c0];     acc[mt][nt][3] = s_b[c0 + 1];
        }
    #pragma unroll 4
    for (int kk = 0; kk < KIN; kk += 8) {
        uint32_t afr[4][4];
        #pragma unroll
        for (int mt = 0; mt < 4; mt++) {
            const float* ap = s_in + (mrow + mt * 16 + r) * SINL + kk + q;
            afr[mt][0] = __float_as_uint(ap[0]);
            afr[mt][1] = __float_as_uint(ap[8 * SINL]);
            afr[mt][2] = __float_as_uint(ap[4]);
            afr[mt][3] = __float_as_uint(ap[8 * SINL + 4]);
        }
        #pragma unroll
        for (int nt = 0; nt < NT; nt++) {
            const float* bp = s_w + (kk + q) * SWL + nwb + nt * 8 + r;
            uint32_t b0 = __float_as_uint(bp[0]);
            uint32_t b1 = __float_as_uint(bp[4 * SWL]);
            MMA_TF32(acc[0][nt], afr[0], b0, b1);
            MMA_TF32(acc[1][nt], afr[1], b0, b1);
            MMA_TF32(acc[2][nt], afr[2], b0, b1);
            MMA_TF32(acc[3][nt], afr[3], b0, b1);
        }
    }
    #pragma unroll
    for (int mt = 0; mt < 4; mt++)
        #pragma unroll
        for (int nt = 0; nt < NT; nt++)
            #pragma unroll
            for (int rr = 0; rr < 2; rr++) {
                int node = base + mrow + mt * 16 + r + 8 * rr;
                if (node < N) {
                    int c0 = nwb + nt * 8 + 2 * q;
                    float2 v;
                    v.x = fmaxf(acc[mt][nt][2 * rr + 0], 0.f);
                    v.y = fmaxf(acc[mt][nt][2 * rr + 1], 0.f);
                    *(float2*)(out + (size_t)node * KOUT + c0) = v;
                }
            }
}

// ---------------- host launcher ----------------
static void* symaddr(const void* sym) {
    void* p = nullptr;
    cudaGetSymbolAddress(&p, sym);
    return p;
}

extern "C" void kernel_launch(void* const* d_in, const int* in_sizes, int n_in,
                              void* d_out, int out_size) {
    const float* x   = (const float*)d_in[0];
    const int*   ei  = (const int*)d_in[1];
    const int N = in_sizes[0] / 64;
    const int E = in_sizes[1] / 2;
    const int* src = ei;

    const float* p1pw  = (const float*)d_in[3];
    const float* p1pb  = (const float*)d_in[4];
    const float* p1wih = (const float*)d_in[5];
    const float* p1whh = (const float*)d_in[6];
    const float* p1bih = (const float*)d_in[7];
    const float* p1bhh = (const float*)d_in[8];
    const float* p1llw = (const float*)d_in[9];
    const float* p1llb = (const float*)d_in[10];
    const float* p1lrw = (const float*)d_in[11];
    const float* p2pw  = (const float*)d_in[12];
    const float* p2pb  = (const float*)d_in[13];
    const float* p2wih = (const float*)d_in[14];
    const float* p2whh = (const float*)d_in[15];
    const float* p2bih = (const float*)d_in[16];
    const float* p2bhh = (const float*)d_in[17];
    const float* p2llw = (const float*)d_in[18];
    const float* p2llb = (const float*)d_in[19];
    const float* p2lrw = (const float*)d_in[20];
    const float* l1w   = (const float*)d_in[21];
    const float* l1b   = (const float*)d_in[22];
    const float* l2w   = (const float*)d_in[23];
    const float* l2b   = (const float*)d_in[24];
    const float* l3w   = (const float*)d_in[25];
    const float* l3b   = (const float*)d_in[26];

    float* xp  = (float*)symaddr(g_xp);
    float* h1  = (float*)symaddr(g_h1);
    float* h2  = (float*)symaddr(g_h2);
    float* t1  = (float*)symaddr(g_t1);
    float* t2  = (float*)symaddr(g_t2);
    float* wc1 = (float*)symaddr(g_wc1);
    float* wc2 = (float*)symaddr(g_wc2);
    float* bs1 = (float*)symaddr(g_bs1);
    float* bs2 = (float*)symaddr(g_bs2);
    float* wo1 = (float*)symaddr(g_wo1);
    float* wo2 = (float*)symaddr(g_wo2);
    float* pT1 = (float*)symaddr(g_pT1);
    float* pT2 = (float*)symaddr(g_pT2);
    float* l1T = (float*)symaddr(g_l1T);
    float* l2T = (float*)symaddr(g_l2T);
    float* l3T = (float*)symaddr(g_l3T);

    const int SM_LSTM = (128 * SW + 128 * SIN + 256) * 4 + 2048 * 4;   // 211968
    const int SM_6464 = (64 * 72 + 128 * 68 + 64) * 4;                 // 53504
    const int SM_L1   = (128 * 200 + 128 * 132 + 192) * 4;             // 170752
    const int SM_L2   = (192 * 72 + 128 * 196 + 64) * 4;               // 155904
    cudaFuncSetAttribute(lstm_mma_kernel<64>,  cudaFuncAttributeMaxDynamicSharedMemorySize, SM_LSTM);
    cudaFuncSetAttribute(lstm_mma_kernel<128>, cudaFuncAttributeMaxDynamicSharedMemorySize, SM_LSTM);
    cudaFuncSetAttribute(mma_linear<64, 64>,   cudaFuncAttributeMaxDynamicSharedMemorySize, SM_6464);
    cudaFuncSetAttribute(mma_linear<128, 192>, cudaFuncAttributeMaxDynamicSharedMemorySize, SM_L1);
    cudaFuncSetAttribute(mma_linear<192, 64>,  cudaFuncAttributeMaxDynamicSharedMemorySize, SM_L2);

    // --- weight prep ---
    k_prep_lstm_perm<<<(128 * 256 + 255) / 256, 256>>>(wc1, bs1, p1wih, p1whh, p1bih, p1bhh);
    k_prep_lstm_perm<<<(128 * 256 + 255) / 256, 256>>>(wc2, bs2, p2wih, p2whh, p2bih, p2bhh);
    k_prep_out<<<(128 * 64 + 255) / 256, 256>>>(wo1, p1llw, p1lrw, 64);
    k_prep_out<<<(128 * 128 + 255) / 256, 256>>>(wo2, p2llw, p2lrw, 128);
    k_transpose_tf32<<<(64 * 64 + 255) / 256, 256>>>(pT1, p1pw, 64, 64);
    k_transpose_tf32<<<(64 * 64 + 255) / 256, 256>>>(pT2, p2pw, 64, 64);
    k_transpose_tf32<<<(128 * 192 + 255) / 256, 256>>>(l1T, l1w, 192, 128);
    k_transpose_tf32<<<(192 * 64 + 255) / 256, 256>>>(l2T, l2w, 64, 192);
    k_transpose_tf32<<<(64 * 64 + 255) / 256, 256>>>(l3T, l3w, 64, 64);

    const int NB = (N + 127) / 128;

    // --- layer 1 ---
    mma_linear<64, 64><<<NB, 256, SM_6464>>>(x, pT1, p1pb, xp, N);
    lstm_mma_kernel<64><<<NB, 256, SM_LSTM>>>(xp, x, src, wc1, bs1, wo1, p1llb, h1, N);
    // --- layer 2 ---
    mma_linear<64, 64><<<NB, 256, SM_6464>>>(h1, pT2, p2pb, xp, N);
    lstm_mma_kernel<128><<<NB, 256, SM_LSTM>>>(xp, h1, src, wc2, bs2, wo2, p2llb, h2, N);
    // --- MLP head ---
    mma_linear<128, 192><<<NB, 256, SM_L1>>>(h2, l1T, l1b, t1, N);
    mma_linear<192, 64><<<NB, 256, SM_L2>>>(t1, l2T, l2b, t2, N);
    mma_linear<64, 64><<<NB, 256, SM_6464>>>(t2, l3T, l3b, (float*)d_out, N);

    // --- edge_index passthrough if the output buffer holds it ---
    long hsz = (long)N * 64;
    if ((long)out_size > hsz) {
        long remaining = (long)out_size - hsz;
        int count = (int)((remaining < (long)2 * E) ? remaining : (long)2 * E);
        k_edge_copy<<<(count + 255) / 256, 256>>>(ei, (float*)d_out + hsz, count);
    }
}